// round 17
// baseline (speedup 1.0000x reference)
#include <cuda_runtime.h>
#include <cuda_bf16.h>
#include <cstdint>

// LorenzSDE ShARK integrator, B = 4,194,304, 5 steps, additive noise.
// HBM-bound streaming (604 MB) at 6.85 TB/s (86.5% DRAM). Every deleted
// sync point has bought bandwidth; this round removes the LAST one:
// warp-autonomous staging. Each warp stages its own 32 elements' dW/dH
// (contiguous 1920B slice -> 120 lane-consecutive float4, fully coalesced)
// into its own smem partition and proceeds after __syncwarp() only.
// No inter-warp coupling: the max-of-4-warps staging skew and the
// __syncthreads STS-drain are gone. Rest frozen from R16: 128-thr one-shot
// CTAs, 12/SM, 15.4KB smem (L1D~44KB), __ldcs/__stcs, direct reg stores.

#define BATCH_TOTAL 4194304
#define NSTEP 5
#define TILE 128                       // batch elements per tile == threads
#define BLK 128
#define NTILES (BATCH_TOTAL / TILE)    // 32768

__device__ __forceinline__ void lorenz_drift(float x, float y, float z,
                                             float& fx, float& fy, float& fz) {
    fx = 10.0f * (y - x);
    fy = x * (28.0f - z) - y;
    fz = x * y - (8.0f / 3.0f) * z;
}

__global__ __launch_bounds__(BLK, 12)
void lorenz_shark_kernel(const float* __restrict__ x,
                         const float* __restrict__ dW,
                         const float* __restrict__ dH,
                         float* __restrict__ out) {
    __shared__ __align__(16) float s_w[TILE * 15];   // 7680 B
    __shared__ __align__(16) float s_h[TILE * 15];   // 7680 B

    const int tid  = threadIdx.x;
    const int wid  = tid >> 5;                       // warp 0..3
    const int lane = tid & 31;
    const size_t base = (size_t)blockIdx.x * TILE;

    // ---- x loaded directly, first (warp covers 384 contiguous bytes) ---
    float y0 = __ldcs(x + (base + tid) * 3 + 0);
    float y1 = __ldcs(x + (base + tid) * 3 + 1);
    float y2 = __ldcs(x + (base + tid) * 3 + 2);

    // ---- warp-autonomous staging: warp w owns elements [w*32, w*32+32).
    // Its dW/dH slice = 480 floats = 120 float4, contiguous in gmem.
    {
        const float4* __restrict__ w4 = (const float4*)(dW + (base + wid * 32) * 15);
        const float4* __restrict__ h4 = (const float4*)(dH + (base + wid * 32) * 15);
        float4* sw4 = (float4*)(s_w + wid * 32 * 15);
        float4* sh4 = (float4*)(s_h + wid * 32 * 15);
#pragma unroll
        for (int i = 0; i < 3; i++) {                // 96 float4
            sw4[lane + i * 32] = __ldcs(&w4[lane + i * 32]);
            sh4[lane + i * 32] = __ldcs(&h4[lane + i * 32]);
        }
        if (lane < 24) {                             // 24 tail float4 each
            sw4[lane + 96] = __ldcs(&w4[lane + 96]);
            sh4[lane + 96] = __ldcs(&h4[lane + 96]);
        }
    }
    __syncwarp();                                    // warp-local only

    const float dt    = 0.01f;
    const float cW    = 0.2f;            // NOISE * sqrt(dt)
    const float cH    = 0.057735026919f; // NOISE * sqrt(dt/12)
    const float c56dt = (5.0f / 6.0f) * 0.01f;
    const float c56   = 5.0f / 6.0f;

#pragma unroll
    for (int s = 0; s < NSTEP; s++) {
        const int wb = tid * (NSTEP * 3) + s * 3;    // stride 15: conflict-free
        float w0 = cW * s_w[wb + 0];
        float w1 = cW * s_w[wb + 1];
        float w2 = cW * s_w[wb + 2];
        float h0 = cH * s_h[wb + 0];
        float h1 = cH * s_h[wb + 1];
        float h2 = cH * s_h[wb + 2];

        // z1 = y + h
        float z0 = y0 + h0, z1 = y1 + h1, z2 = y2 + h2;
        float f10, f11, f12;
        lorenz_drift(z0, z1, z2, f10, f11, f12);

        // z2 = y + (5/6)dt*f1 + (5/6)*w + h
        float u0 = y0 + c56dt * f10 + c56 * w0 + h0;
        float u1 = y1 + c56dt * f11 + c56 * w1 + h1;
        float u2 = y2 + c56dt * f12 + c56 * w2 + h2;
        float f20, f21, f22;
        lorenz_drift(u0, u1, u2, f20, f21, f22);

        // y = y + dt*(0.4*f1 + 0.6*f2) + w
        y0 = y0 + dt * (0.4f * f10 + 0.6f * f20) + w0;
        y1 = y1 + dt * (0.4f * f11 + 0.6f * f21) + w1;
        y2 = y2 + dt * (0.4f * f12 + 0.6f * f22) + w2;
    }

    // ---- direct store: 3 stride-3 STG.32 per thread; per warp these
    // cover 384 contiguous bytes -> write coalescer emits full lines.
    float* o = out + (base + tid) * 3;
    __stcs(o + 0, y0);
    __stcs(o + 1, y1);
    __stcs(o + 2, y2);
}

extern "C" void kernel_launch(void* const* d_in, const int* in_sizes, int n_in,
                              void* d_out, int out_size) {
    const float* x  = (const float*)d_in[0];   // [B, 3]
    const float* dW = (const float*)d_in[1];   // [B, 5, 3]
    const float* dH = (const float*)d_in[2];   // [B, 5, 3]
    float* out = (float*)d_out;                // [B, 3]

    lorenz_shark_kernel<<<NTILES, BLK>>>(x, dW, dH, out);
}